// round 11
// baseline (speedup 1.0000x reference)
#include <cuda_runtime.h>

#define RES 256
#define CELLS (RES*RES)
#define NCH 32
#define ACCSZ (CELLS*NCH)
#define NPLANE 3
#define FULLMASK 0xFFFFFFFFu

// Scratch (device globals: zero-initialized at module load).
// INVARIANT: every kernel_launch execution leaves g_acc/g_cnt/g_sum/g_ss
// zeroed again (reduce re-zeroes acc/cnt after consuming; k_rst re-zeroes stats).
__device__ float  g_acc [NPLANE*ACCSZ];   // [plane][cell][ch]
__device__ float  g_cnt [NPLANE*CELLS];   // [plane][cell]
__device__ float  g_newT[NPLANE*ACCSZ];   // [plane][ch][cell]  (transposed, /count)
__device__ double g_sum [NPLANE];
__device__ double g_ss  [NPLANE];

// ---------------------------------------------------------------- scatter
// one warp per gaussian; lane = channel. 4 coalesced 128B RED lines per plane.
// (measured best: LTS RMW byte-bound floor)
__global__ void k_scatter(const float* __restrict__ xyz,
                          const float* __restrict__ feats, int n) {
    int w    = (blockIdx.x * blockDim.x + threadIdx.x) >> 5;
    int lane = threadIdx.x & 31;
    if (w >= n) return;

    float gx = __ldg(xyz + 3*w + 0);
    float gy = __ldg(xyz + 3*w + 1);
    float gz = __ldg(xyz + 3*w + 2);
    float x = fminf(fmaxf((gx + 1.f) * 0.5f, 0.f), 0.999f) * (float)(RES - 1);
    float y = fminf(fmaxf((gy + 1.f) * 0.5f, 0.f), 0.999f) * (float)(RES - 1);
    float z = fminf(fmaxf((gz + 1.f) * 0.5f, 0.f), 0.999f) * (float)(RES - 1);

    #pragma unroll
    for (int p = 0; p < 3; p++) {
        float px = (p == 2) ? y : x;              // xy:(x,y) xz:(x,z) yz:(y,z)
        float py = (p == 0) ? y : z;

        int ix0 = (int)floorf(px);
        int iy0 = (int)floorf(py);
        int ix0c = min(max(ix0, 0), RES-1);
        int ix1c = min(ix0 + 1,    RES-1);
        int iy0c = min(max(iy0, 0), RES-1);
        int iy1c = min(iy0 + 1,    RES-1);

        float wx0 = fminf(fmaxf((float)ix1c - px, 0.f), 1.f);
        float wx1 = fminf(fmaxf(px - (float)ix0c, 0.f), 1.f);
        float wy0 = fminf(fmaxf((float)iy1c - py, 0.f), 1.f);
        float wy1 = fminf(fmaxf(py - (float)iy0c, 0.f), 1.f);

        int l0 = iy0c*RES + ix0c;
        int l1 = iy1c*RES + ix0c;
        int l2 = iy0c*RES + ix1c;
        int l3 = iy1c*RES + ix1c;
        float w00 = wx0*wy0, w01 = wx0*wy1, w10 = wx1*wy0, w11 = wx1*wy1;

        float f = __ldg(feats + (size_t)w*96 + p*32 + lane);
        float* base = g_acc + (size_t)p*ACCSZ;
        atomicAdd(base + (size_t)l0*NCH + lane, f*w00);
        atomicAdd(base + (size_t)l1*NCH + lane, f*w01);
        atomicAdd(base + (size_t)l2*NCH + lane, f*w10);
        atomicAdd(base + (size_t)l3*NCH + lane, f*w11);

        if (lane < 4) {
            int ll = (lane == 0) ? l0 : (lane == 1) ? l1 : (lane == 2) ? l2 : l3;
            atomicAdd(g_cnt + p*CELLS + ll, 1.0f);
        }
    }
}

// ---------------------------------------------------------------- reduce + transpose (+ re-zero)
__global__ void k_reduce() {
    int p    = blockIdx.y;
    int cell = blockIdx.x * blockDim.x + threadIdx.x;

    float cnt = g_cnt[p*CELLS + cell];
    g_cnt[p*CELLS + cell] = 0.f;                 // restore invariant
    float inv = 1.f / (cnt + 1e-6f);
    float4* a = (float4*)(g_acc + (size_t)p*ACCSZ + (size_t)cell*NCH);
    float* nt = g_newT + (size_t)p*ACCSZ;

    const float4 z4 = make_float4(0.f, 0.f, 0.f, 0.f);
    float s = 0.f, ss = 0.f;
    #pragma unroll
    for (int i = 0; i < 8; i++) {
        float4 v = a[i];
        a[i] = z4;                               // restore invariant
        float n0 = v.x*inv, n1 = v.y*inv, n2 = v.z*inv, n3 = v.w*inv;
        s  += n0 + n1 + n2 + n3;
        ss += n0*n0 + n1*n1 + n2*n2 + n3*n3;
        nt[(size_t)(i*4+0)*CELLS + cell] = n0;
        nt[(size_t)(i*4+1)*CELLS + cell] = n1;
        nt[(size_t)(i*4+2)*CELLS + cell] = n2;
        nt[(size_t)(i*4+3)*CELLS + cell] = n3;
    }

    double ds = (double)s, dss = (double)ss;
    #pragma unroll
    for (int off = 16; off; off >>= 1) {
        ds  += __shfl_down_sync(FULLMASK, ds,  off);
        dss += __shfl_down_sync(FULLMASK, dss, off);
    }
    __shared__ double shs[8], shss[8];
    int wid = threadIdx.x >> 5;
    if ((threadIdx.x & 31) == 0) { shs[wid] = ds; shss[wid] = dss; }
    __syncthreads();
    if (threadIdx.x == 0) {
        double t = 0.0, tt = 0.0;
        for (int i = 0; i < 8; i++) { t += shs[i]; tt += shss[i]; }
        atomicAdd(&g_sum[p], t);
        atomicAdd(&g_ss[p], tt);
    }
}

// ---------------------------------------------------------------- normalize + blur + residual
// One-barrier blur, float4 staging: block = 256 threads, one (p,c,32-row strip).
// Stage LN'd 36x256 strip via float4 loads + STS.128 into smem (data at col 4,
// 16B aligned), sync once, then rolling horizontal/vertical 5-taps from smem.
#define STRIP 32
__global__ void k_blur(const float* __restrict__ p_xy,
                       const float* __restrict__ p_xz,
                       const float* __restrict__ p_yz,
                       const float* __restrict__ lnw,
                       const float* __restrict__ lnb,
                       float* __restrict__ out) {
    const float W0 = 0.054488684549642945f;
    const float W1 = 0.2442013422000340f;
    const float W2 = 0.4026199464998460f;

    int pc = blockIdx.y;
    int p  = pc >> 5;
    int c  = pc & 31;
    int x  = threadIdx.x;

    double nelem = (double)ACCSZ;
    double mu_d  = g_sum[p] / nelem;
    double var_d = g_ss[p] / nelem - mu_d * mu_d;
    float mu  = (float)mu_d;
    float inv = (float)(1.0 / sqrt(var_d + 1e-5));

    const float4* nt4 = (const float4*)(g_newT + (size_t)p*ACCSZ + (size_t)c*CELLS);
    const float4* lw4 = (const float4*)(lnw + (size_t)c*CELLS);
    const float4* lb4 = (const float4*)(lnb + (size_t)c*CELLS);
    const float* plane = ((p == 0) ? p_xy : (p == 1) ? p_xz : p_yz) + (size_t)c*CELLS;
    float*       o     = out + (size_t)p*ACCSZ + (size_t)c*CELLS;

    __shared__ float s[36][264];     // data cols 4..259; pads 2,3,260,261

    if (x < 36) { s[x][2] = 0.f; s[x][3] = 0.f; s[x][260] = 0.f; s[x][261] = 0.f; }

    int y0 = blockIdx.x * STRIP;

    // stage 36 rows (y0-2 .. y0+33): 4 rows x 64 float4-columns per iteration
    int rsub = x >> 6;         // 0..3
    int q    = x & 63;         // float4 column
    #pragma unroll
    for (int it = 0; it < 9; it++) {
        int r = it*4 + rsub;
        int y = y0 - 2 + r;
        float4 res = make_float4(0.f, 0.f, 0.f, 0.f);
        if ((unsigned)y < (unsigned)RES) {
            int i4 = y*64 + q;
            float4 v = nt4[i4], w = lw4[i4], b = lb4[i4];
            res.x = (v.x - mu) * inv * w.x + b.x;
            res.y = (v.y - mu) * inv * w.y + b.y;
            res.z = (v.z - mu) * inv * w.z + b.z;
            res.w = (v.w - mu) * inv * w.w + b.w;
        }
        *(float4*)&s[r][4 + q*4] = res;
    }
    __syncthreads();

    // horizontal 5-tap from smem (pixel x lives at col x+4)
    auto hrow = [&](int r) -> float {
        return W0*(s[r][x+2] + s[r][x+6])
             + W1*(s[r][x+3] + s[r][x+5])
             + W2* s[r][x+4];
    };

    float h0 = hrow(0), h1 = hrow(1), h2 = hrow(2), h3 = hrow(3), h4;

    #pragma unroll
    for (int i = 0; i < STRIP; i++) {
        h4 = hrow(i + 4);
        float r = W0*(h0 + h4) + W1*(h1 + h3) + W2*h2;
        int lin = (y0 + i)*RES + x;
        o[lin] = r + plane[lin];
        h0 = h1; h1 = h2; h2 = h3; h3 = h4;
    }
}

// ---------------------------------------------------------------- reset stats for next replay
__global__ void k_rst() {
    int i = threadIdx.x;
    if (i < NPLANE) { g_sum[i] = 0.0; g_ss[i] = 0.0; }
}

// ---------------------------------------------------------------- launch
extern "C" void kernel_launch(void* const* d_in, const int* in_sizes, int n_in,
                              void* d_out, int out_size) {
    const float* plane_xy = (const float*)d_in[0];
    const float* plane_xz = (const float*)d_in[1];
    const float* plane_yz = (const float*)d_in[2];
    const float* ln_w     = (const float*)d_in[3];
    const float* ln_b     = (const float*)d_in[4];
    const float* feats    = (const float*)d_in[5];
    const float* xyz      = (const float*)d_in[6];
    float* out = (float*)d_out;
    int n = in_sizes[6] / 3;   // 500000

    {
        int threads = 256;
        long long total = (long long)n * 32;
        int blocks = (int)((total + threads - 1) / threads);
        k_scatter<<<blocks, threads>>>(xyz, feats, n);
    }
    k_reduce<<<dim3(CELLS/256, NPLANE), 256>>>();
    k_blur<<<dim3(RES/STRIP, NPLANE*NCH), 256>>>(
        plane_xy, plane_xz, plane_yz, ln_w, ln_b, out);
    k_rst<<<1, 32>>>();
}

// round 12
// speedup vs baseline: 1.3995x; 1.3995x over previous
#include <cuda_runtime.h>

#define RES 256
#define CELLS (RES*RES)
#define NCH 32
#define ACCSZ (CELLS*NCH)
#define NPLANE 3
#define FULLMASK 0xFFFFFFFFu

// Scratch (device globals: allocation-free rule)
__device__ float  g_acc [NPLANE*ACCSZ];   // [plane][cell][ch]
__device__ float  g_cnt [NPLANE*CELLS];   // [plane][cell]
__device__ float  g_newT[NPLANE*ACCSZ];   // [plane][ch][cell]  (transposed, /count)
__device__ double g_sum [NPLANE];
__device__ double g_ss  [NPLANE];

// ---------------------------------------------------------------- zero (float4)
// NOTE: also load-bearing as an L2 pre-warm for the scatter's atomics —
// removing it (R11) pushed scatter RMWs to DRAM and cost +70us.
__global__ void k_zero() {
    int i = blockIdx.x * blockDim.x + threadIdx.x;
    int stride = gridDim.x * blockDim.x;
    float4 z = make_float4(0.f, 0.f, 0.f, 0.f);
    float4* a = (float4*)g_acc;
    float4* c = (float4*)g_cnt;
    for (int j = i; j < NPLANE*ACCSZ/4; j += stride) a[j] = z;
    for (int j = i; j < NPLANE*CELLS/4; j += stride) c[j] = z;
    if (i < NPLANE) { g_sum[i] = 0.0; g_ss[i] = 0.0; }
}

// ---------------------------------------------------------------- scatter
// one warp per gaussian; lane = channel. 4 coalesced 128B RED lines per plane.
// (measured best: LTS RMW byte-bound floor)
__global__ void k_scatter(const float* __restrict__ xyz,
                          const float* __restrict__ feats, int n) {
    int w    = (blockIdx.x * blockDim.x + threadIdx.x) >> 5;
    int lane = threadIdx.x & 31;
    if (w >= n) return;

    float gx = __ldg(xyz + 3*w + 0);
    float gy = __ldg(xyz + 3*w + 1);
    float gz = __ldg(xyz + 3*w + 2);
    float x = fminf(fmaxf((gx + 1.f) * 0.5f, 0.f), 0.999f) * (float)(RES - 1);
    float y = fminf(fmaxf((gy + 1.f) * 0.5f, 0.f), 0.999f) * (float)(RES - 1);
    float z = fminf(fmaxf((gz + 1.f) * 0.5f, 0.f), 0.999f) * (float)(RES - 1);

    #pragma unroll
    for (int p = 0; p < 3; p++) {
        float px = (p == 2) ? y : x;              // xy:(x,y) xz:(x,z) yz:(y,z)
        float py = (p == 0) ? y : z;

        int ix0 = (int)floorf(px);
        int iy0 = (int)floorf(py);
        int ix0c = min(max(ix0, 0), RES-1);
        int ix1c = min(ix0 + 1,    RES-1);
        int iy0c = min(max(iy0, 0), RES-1);
        int iy1c = min(iy0 + 1,    RES-1);

        float wx0 = fminf(fmaxf((float)ix1c - px, 0.f), 1.f);
        float wx1 = fminf(fmaxf(px - (float)ix0c, 0.f), 1.f);
        float wy0 = fminf(fmaxf((float)iy1c - py, 0.f), 1.f);
        float wy1 = fminf(fmaxf(py - (float)iy0c, 0.f), 1.f);

        int l0 = iy0c*RES + ix0c;
        int l1 = iy1c*RES + ix0c;
        int l2 = iy0c*RES + ix1c;
        int l3 = iy1c*RES + ix1c;
        float w00 = wx0*wy0, w01 = wx0*wy1, w10 = wx1*wy0, w11 = wx1*wy1;

        float f = __ldg(feats + (size_t)w*96 + p*32 + lane);
        float* base = g_acc + (size_t)p*ACCSZ;
        atomicAdd(base + (size_t)l0*NCH + lane, f*w00);
        atomicAdd(base + (size_t)l1*NCH + lane, f*w01);
        atomicAdd(base + (size_t)l2*NCH + lane, f*w10);
        atomicAdd(base + (size_t)l3*NCH + lane, f*w11);

        if (lane < 4) {
            int ll = (lane == 0) ? l0 : (lane == 1) ? l1 : (lane == 2) ? l2 : l3;
            atomicAdd(g_cnt + p*CELLS + ll, 1.0f);
        }
    }
}

// ---------------------------------------------------------------- reduce + transpose
__global__ void k_reduce() {
    int p    = blockIdx.y;
    int cell = blockIdx.x * blockDim.x + threadIdx.x;

    float cnt = g_cnt[p*CELLS + cell];
    float inv = 1.f / (cnt + 1e-6f);
    const float4* a = (const float4*)(g_acc + (size_t)p*ACCSZ + (size_t)cell*NCH);
    float* nt = g_newT + (size_t)p*ACCSZ;

    float s = 0.f, ss = 0.f;
    #pragma unroll
    for (int i = 0; i < 8; i++) {
        float4 v = a[i];
        float n0 = v.x*inv, n1 = v.y*inv, n2 = v.z*inv, n3 = v.w*inv;
        s  += n0 + n1 + n2 + n3;
        ss += n0*n0 + n1*n1 + n2*n2 + n3*n3;
        nt[(size_t)(i*4+0)*CELLS + cell] = n0;
        nt[(size_t)(i*4+1)*CELLS + cell] = n1;
        nt[(size_t)(i*4+2)*CELLS + cell] = n2;
        nt[(size_t)(i*4+3)*CELLS + cell] = n3;
    }

    double ds = (double)s, dss = (double)ss;
    #pragma unroll
    for (int off = 16; off; off >>= 1) {
        ds  += __shfl_down_sync(FULLMASK, ds,  off);
        dss += __shfl_down_sync(FULLMASK, dss, off);
    }
    __shared__ double shs[8], shss[8];
    int wid = threadIdx.x >> 5;
    if ((threadIdx.x & 31) == 0) { shs[wid] = ds; shss[wid] = dss; }
    __syncthreads();
    if (threadIdx.x == 0) {
        double t = 0.0, tt = 0.0;
        for (int i = 0; i < 8; i++) { t += shs[i]; tt += shss[i]; }
        atomicAdd(&g_sum[p], t);
        atomicAdd(&g_ss[p], tt);
    }
}

// ---------------------------------------------------------------- normalize + blur + residual
// One-barrier blur, float4 staging: block = 256 threads, one (p,c,32-row strip).
// Stage LN'd 36x256 strip via float4 loads + STS.128 into smem (data at col 4,
// 16B aligned), sync once, then rolling horizontal/vertical 5-taps from smem.
#define STRIP 32
__global__ void k_blur(const float* __restrict__ p_xy,
                       const float* __restrict__ p_xz,
                       const float* __restrict__ p_yz,
                       const float* __restrict__ lnw,
                       const float* __restrict__ lnb,
                       float* __restrict__ out) {
    const float W0 = 0.054488684549642945f;
    const float W1 = 0.2442013422000340f;
    const float W2 = 0.4026199464998460f;

    int pc = blockIdx.y;
    int p  = pc >> 5;
    int c  = pc & 31;
    int x  = threadIdx.x;

    double nelem = (double)ACCSZ;
    double mu_d  = g_sum[p] / nelem;
    double var_d = g_ss[p] / nelem - mu_d * mu_d;
    float mu  = (float)mu_d;
    float inv = (float)(1.0 / sqrt(var_d + 1e-5));

    const float4* nt4 = (const float4*)(g_newT + (size_t)p*ACCSZ + (size_t)c*CELLS);
    const float4* lw4 = (const float4*)(lnw + (size_t)c*CELLS);
    const float4* lb4 = (const float4*)(lnb + (size_t)c*CELLS);
    const float* plane = ((p == 0) ? p_xy : (p == 1) ? p_xz : p_yz) + (size_t)c*CELLS;
    float*       o     = out + (size_t)p*ACCSZ + (size_t)c*CELLS;

    __shared__ float s[36][264];     // data cols 4..259; pads 2,3,260,261

    if (x < 36) { s[x][2] = 0.f; s[x][3] = 0.f; s[x][260] = 0.f; s[x][261] = 0.f; }

    int y0 = blockIdx.x * STRIP;

    // stage 36 rows (y0-2 .. y0+33): 4 rows x 64 float4-columns per iteration
    int rsub = x >> 6;         // 0..3
    int q    = x & 63;         // float4 column
    #pragma unroll
    for (int it = 0; it < 9; it++) {
        int r = it*4 + rsub;
        int y = y0 - 2 + r;
        float4 res = make_float4(0.f, 0.f, 0.f, 0.f);
        if ((unsigned)y < (unsigned)RES) {
            int i4 = y*64 + q;
            float4 v = nt4[i4], w = lw4[i4], b = lb4[i4];
            res.x = (v.x - mu) * inv * w.x + b.x;
            res.y = (v.y - mu) * inv * w.y + b.y;
            res.z = (v.z - mu) * inv * w.z + b.z;
            res.w = (v.w - mu) * inv * w.w + b.w;
        }
        *(float4*)&s[r][4 + q*4] = res;
    }
    __syncthreads();

    // horizontal 5-tap from smem (pixel x lives at col x+4)
    auto hrow = [&](int r) -> float {
        return W0*(s[r][x+2] + s[r][x+6])
             + W1*(s[r][x+3] + s[r][x+5])
             + W2* s[r][x+4];
    };

    float h0 = hrow(0), h1 = hrow(1), h2 = hrow(2), h3 = hrow(3), h4;

    #pragma unroll
    for (int i = 0; i < STRIP; i++) {
        h4 = hrow(i + 4);
        float r = W0*(h0 + h4) + W1*(h1 + h3) + W2*h2;
        int lin = (y0 + i)*RES + x;
        o[lin] = r + plane[lin];
        h0 = h1; h1 = h2; h2 = h3; h3 = h4;
    }
}

// ---------------------------------------------------------------- launch
extern "C" void kernel_launch(void* const* d_in, const int* in_sizes, int n_in,
                              void* d_out, int out_size) {
    const float* plane_xy = (const float*)d_in[0];
    const float* plane_xz = (const float*)d_in[1];
    const float* plane_yz = (const float*)d_in[2];
    const float* ln_w     = (const float*)d_in[3];
    const float* ln_b     = (const float*)d_in[4];
    const float* feats    = (const float*)d_in[5];
    const float* xyz      = (const float*)d_in[6];
    float* out = (float*)d_out;
    int n = in_sizes[6] / 3;   // 500000

    k_zero<<<1024, 256>>>();
    {
        int threads = 256;
        long long total = (long long)n * 32;
        int blocks = (int)((total + threads - 1) / threads);
        k_scatter<<<blocks, threads>>>(xyz, feats, n);
    }
    k_reduce<<<dim3(CELLS/256, NPLANE), 256>>>();
    k_blur<<<dim3(RES/STRIP, NPLANE*NCH), 256>>>(
        plane_xy, plane_xz, plane_yz, ln_w, ln_b, out);
}